// round 10
// baseline (speedup 1.0000x reference)
#include <cuda_runtime.h>
#include <cuda_fp16.h>
#include <cstdint>

#define QDIM 4096   // q_dim (output rows i)
#define NDIM 4096   // contraction of GEMM1 (n/k)
#define MDIM 8192   // softmax dim / contraction of GEMM2 (j)
#define VDIM 4096   // v_dim (output cols v)

// ---------------- scratch (static device globals) ---------------------------
__device__ __half g_Qh[(size_t)NDIM * QDIM];   // Qh[k][i] = (half) Q[k][i]  (native layout)
__device__ __half g_Kh[(size_t)NDIM * MDIM];   // Kh[k][j] = (half) K[k][j]  (native layout)
__device__ __half g_Vc[(size_t)VDIM * MDIM];   // Vc[v][j] = (half) V[v][j]
__device__ __half g_P [(size_t)QDIM * MDIM];   // exp(s) UNNORMALIZED fp16
__device__ float  g_rinv[QDIM];                // 1 / row sums

// ---------------- helpers ----------------------------------------------------
__device__ __forceinline__ uint32_t smem_u32(const void* p) {
    uint32_t a;
    asm("{ .reg .u64 t; cvta.to.shared.u64 t, %1; cvt.u32.u64 %0, t; }" : "=r"(a) : "l"(p));
    return a;
}
__device__ __forceinline__ void cp16(uint32_t dst, const void* src) {
    asm volatile("cp.async.cg.shared.global [%0], [%1], 16;" :: "r"(dst), "l"(src));
}
__device__ __forceinline__ void ldsm4(uint32_t& r0, uint32_t& r1, uint32_t& r2, uint32_t& r3,
                                      uint32_t addr) {
    asm volatile("ldmatrix.sync.aligned.m8n8.x4.shared.b16 {%0,%1,%2,%3}, [%4];"
                 : "=r"(r0), "=r"(r1), "=r"(r2), "=r"(r3) : "r"(addr));
}
__device__ __forceinline__ void ldsm4t(uint32_t& r0, uint32_t& r1, uint32_t& r2, uint32_t& r3,
                                       uint32_t addr) {
    asm volatile("ldmatrix.sync.aligned.m8n8.x4.trans.shared.b16 {%0,%1,%2,%3}, [%4];"
                 : "=r"(r0), "=r"(r1), "=r"(r2), "=r"(r3) : "r"(addr));
}
__device__ __forceinline__ void mma16816(float* d, uint32_t a0, uint32_t a1, uint32_t a2,
                                         uint32_t a3, uint32_t b0, uint32_t b1) {
    asm volatile(
        "mma.sync.aligned.m16n8k16.row.col.f32.f16.f16.f32 "
        "{%0,%1,%2,%3}, {%4,%5,%6,%7}, {%8,%9}, {%0,%1,%2,%3};"
        : "+f"(d[0]), "+f"(d[1]), "+f"(d[2]), "+f"(d[3])
        : "r"(a0), "r"(a1), "r"(a2), "r"(a3), "r"(b0), "r"(b1));
}

// ---------------- preprocessing: straight fp32 -> fp16 convert ----------------
__global__ void convert_f2h(const float* __restrict__ in, __half* __restrict__ out, size_t n) {
    size_t i = ((size_t)blockIdx.x * blockDim.x + threadIdx.x) * 4;
    if (i + 3 < n) {
        float4 v = *reinterpret_cast<const float4*>(in + i);
        *reinterpret_cast<__half2*>(out + i)     = __floats2half2_rn(v.x, v.y);
        *reinterpret_cast<__half2*>(out + i + 2) = __floats2half2_rn(v.z, v.w);
    }
}

// =============================================================================
// GEMM1 (trans-load): S[i][j] = sum_k Qh[k][i] * Kh[k][j]; C = exp(scale*S) fp16
// 512 thr, CTA tile 128(i) x 256(j), k-chunk 64, 4 stages, 1 CTA/SM.
// Smem tiles are k-major: A = 64k x 128i (256B rows), B = 64k x 256j (512B rows).
// Fragments via ldmatrix.x4.trans; tile order matches non-trans fragment order.
// =============================================================================
#define BM1 128
#define BN1 256
#define BKC 64
#define STAGES1 4
#define A1_BYTES (BKC * BM1 * 2)              // 16 KB
#define B1_BYTES (BKC * BN1 * 2)              // 32 KB
#define STG1_BYTES (A1_BYTES + B1_BYTES)      // 48 KB
#define SMEM1_SZ (STAGES1 * STG1_BYTES)       // 192 KB

__global__ __launch_bounds__(512, 1)
void gemm1_mma(const __half* __restrict__ A, const __half* __restrict__ B,
               __half* __restrict__ C, int M, int N, int K) {
    extern __shared__ char smem[];
    const uint32_t sb = smem_u32(smem);
    const int tid = threadIdx.x;
    const int wid = tid >> 5;
    const int lane = tid & 31;
    const int wm = wid & 3;            // 4 warps over M -> 32 rows (i)
    const int wn = wid >> 2;           // 4 warps over N -> 64 cols (j)
    const size_t m0 = (size_t)blockIdx.y * BM1;
    const size_t n0 = (size_t)blockIdx.x * BN1;
    const int nk = K / BKC;

    // cp.async mapping (store chunk c of k-row at ((c ^ (k&7))<<4))
    const int ca = tid & 15, ka = tid >> 4;     // A: 16 chunks/row, rows 0..31 (+32)
    const int cb = tid & 31, kb = tid >> 5;     // B: 32 chunks/row, rows 0..15 (+16..)

    auto load_stage = [&](int c, int buf) {
        const uint32_t abase = sb + buf * STG1_BYTES;
        const uint32_t bbase = abase + A1_BYTES;
        const size_t k0 = (size_t)c * BKC;
        #pragma unroll
        for (int i = 0; i < 2; i++) {
            int k = ka + i * 32;
            cp16(abase + k * 256 + (((uint32_t)(ca ^ (k & 7))) << 4),
                 A + (k0 + k) * (size_t)M + m0 + ca * 8);
        }
        #pragma unroll
        for (int i = 0; i < 4; i++) {
            int k = kb + i * 16;
            cp16(bbase + k * 512 + (((uint32_t)(cb ^ (k & 7))) << 4),
                 B + (k0 + k) * (size_t)N + n0 + cb * 8);
        }
        asm volatile("cp.async.commit_group;" ::: "memory");
    };

    float acc[2][8][4];
    #pragma unroll
    for (int i = 0; i < 2; i++)
        #pragma unroll
        for (int j = 0; j < 8; j++)
            #pragma unroll
            for (int r = 0; r < 4; r++) acc[i][j][r] = 0.0f;

    #pragma unroll
    for (int s = 0; s < STAGES1 - 1; s++) load_stage(s, s);

    // ldmatrix.trans lane addressing:
    // lane tile group t = lane>>3 maps to (k +((t>>1)*8), col +((t&1)*8));
    // r = lane&7 is the k-row within the 8-row tile, and (k_local & 7) == r.
    const uint32_t t = lane >> 3;
    const uint32_t r = lane & 7;
    const uint32_t arow = ((t >> 1) * 8 + r) * 256;   // byte row offset inside k16 block
    const uint32_t brow = ((t >> 1) * 8 + r) * 512;
    uint32_t achk[2], bchk[4];
    #pragma unroll
    for (int mi = 0; mi < 2; mi++)
        achk[mi] = (((uint32_t)(wm * 4 + mi * 2) + (t & 1)) ^ r) << 4;
    #pragma unroll
    for (int ni = 0; ni < 4; ni++)
        bchk[ni] = (((uint32_t)(wn * 8 + ni * 2) + (t & 1)) ^ r) << 4;

    for (int it = 0; it < nk; it++) {
        const int rem = nk - 1 - it;
        if (rem >= 2)      asm volatile("cp.async.wait_group 2;" ::: "memory");
        else if (rem == 1) asm volatile("cp.async.wait_group 1;" ::: "memory");
        else               asm volatile("cp.async.wait_group 0;" ::: "memory");
        __syncthreads();
        if (it + STAGES1 - 1 < nk) load_stage(it + STAGES1 - 1, (it + STAGES1 - 1) % STAGES1);

        const uint32_t abase = sb + (it % STAGES1) * STG1_BYTES;
        const uint32_t bbase = abase + A1_BYTES;

        #pragma unroll
        for (int k16 = 0; k16 < 4; k16++) {
            uint32_t a[2][4], b[4][4];
            #pragma unroll
            for (int mi = 0; mi < 2; mi++)
                ldsm4t(a[mi][0], a[mi][1], a[mi][2], a[mi][3],
                       abase + k16 * 4096 + arow + achk[mi]);
            #pragma unroll
            for (int ni = 0; ni < 4; ni++)
                ldsm4t(b[ni][0], b[ni][1], b[ni][2], b[ni][3],
                       bbase + k16 * 8192 + brow + bchk[ni]);
            #pragma unroll
            for (int mi = 0; mi < 2; mi++)
                #pragma unroll
                for (int nj = 0; nj < 8; nj++)
                    mma16816(acc[mi][nj], a[mi][0], a[mi][1], a[mi][2], a[mi][3],
                             b[nj >> 1][nj & 1], b[nj >> 1][(nj & 1) + 2]);
        }
    }

    const float scale = 0.015625f;     // 1/sqrt(4096)
    #pragma unroll
    for (int mi = 0; mi < 2; mi++) {
        const size_t r0 = m0 + wm * 32 + mi * 16 + (lane >> 2);
        const size_t r1 = r0 + 8;
        #pragma unroll
        for (int nj = 0; nj < 8; nj++) {
            const size_t col = n0 + wn * 64 + nj * 8 + (lane & 3) * 2;
            float* c = acc[mi][nj];
            *reinterpret_cast<__half2*>(&C[r0 * (size_t)N + col]) =
                __floats2half2_rn(__expf(c[0] * scale), __expf(c[1] * scale));
            *reinterpret_cast<__half2*>(&C[r1 * (size_t)N + col]) =
                __floats2half2_rn(__expf(c[2] * scale), __expf(c[3] * scale));
        }
    }
}

// =============================================================================
// GEMM2: 256 thr, tile 64x128, warp 32x32 (2x4), 4 stages, 2 CTAs/SM.
// grid 2048 CTAs -> 6.9 waves (tail waste halved). C = acc * rinv[row] fp32
// =============================================================================
#define BM2 64
#define BN2 128
#define STAGES2 4
#define STG2_BYTES ((BM2 + BN2) * 128)        // 24 KB
#define SMEM2_SZ (STAGES2 * STG2_BYTES)       // 96 KB

__global__ __launch_bounds__(256, 2)
void gemm2_mma(const __half* __restrict__ A, const __half* __restrict__ B,
               float* __restrict__ C, int M, int N, int K,
               const float* __restrict__ rinv) {
    extern __shared__ char smem[];
    const uint32_t sb = smem_u32(smem);
    const int tid = threadIdx.x;
    const int wid = tid >> 5;          // 0..7
    const int lane = tid & 31;
    const int wm = wid & 1;            // 2 warps over M -> 32 rows
    const int wn = wid >> 1;           // 4 warps over N -> 32 cols
    const size_t m0 = (size_t)blockIdx.y * BM2;
    const size_t n0 = (size_t)blockIdx.x * BN2;
    const int nk = K / BKC;

    const int ldrow = tid >> 3;        // 0..31
    const int ldc16 = tid & 7;
    const uint32_t swz_st = ((uint32_t)ldc16 ^ ((uint32_t)ldrow & 7)) << 4;

    auto load_stage = [&](int c, int buf) {
        const uint32_t abase = sb + buf * STG2_BYTES;
        const uint32_t bbase = abase + BM2 * 128;
        const size_t k0 = (size_t)c * BKC;
        #pragma unroll
        for (int i = 0; i < 2; i++) {                  // A: 64 rows
            int row = ldrow + i * 32;
            cp16(abase + row * 128 + swz_st, A + (m0 + row) * (size_t)K + k0 + ldc16 * 8);
        }
        #pragma unroll
        for (int i = 0; i < 4; i++) {                  // B: 128 rows
            int row = ldrow + i * 32;
            cp16(bbase + row * 128 + swz_st, B + (n0 + row) * (size_t)K + k0 + ldc16 * 8);
        }
        asm volatile("cp.async.commit_group;" ::: "memory");
    };

    float acc[2][4][4];
    #pragma unroll
    for (int i = 0; i < 2; i++)
        #pragma unroll
        for (int j = 0; j < 4; j++)
            #pragma unroll
            for (int r = 0; r < 4; r++) acc[i][j][r] = 0.0f;

    #pragma unroll
    for (int s = 0; s < STAGES2 - 1; s++) load_stage(s, s);

    const uint32_t lrow = lane & 15;
    const uint32_t lhalf = lane >> 4;
    const uint32_t lswz = lane & 7;
    const uint32_t a_rowbyte = (wm * 32 + lrow) * 128;
    const uint32_t b_rowbyte = (wn * 32 + lrow) * 128;
    uint32_t coff[4];
    #pragma unroll
    for (int k16 = 0; k16 < 4; k16++)
        coff[k16] = (((uint32_t)k16 * 2 + lhalf) ^ lswz) << 4;

    for (int it = 0; it < nk; it++) {
        const int rem = nk - 1 - it;
        if (rem >= 2)      asm volatile("cp.async.wait_group 2;" ::: "memory");
        else if (rem == 1) asm volatile("cp.async.wait_group 1;" ::: "memory");
        else               asm volatile("cp.async.wait_group 0;" ::: "memory");
        __syncthreads();
        if (it + STAGES2 - 1 < nk) load_stage(it + STAGES2 - 1, (it + STAGES2 - 1) % STAGES2);

        const uint32_t abase = sb + (it % STAGES2) * STG2_BYTES;
        const uint32_t bbase = abase + BM2 * 128;

        #pragma unroll
        for (int k16 = 0; k16 < 4; k16++) {
            uint32_t a[2][4], b[2][4];
            #pragma unroll
            for (int mi = 0; mi < 2; mi++)
                ldsm4(a[mi][0], a[mi][1], a[mi][2], a[mi][3],
                      abase + a_rowbyte + mi * 2048 + coff[k16]);
            #pragma unroll
            for (int ni = 0; ni < 2; ni++)
                ldsm4(b[ni][0], b[ni][1], b[ni][2], b[ni][3],
                      bbase + b_rowbyte + ni * 2048 + coff[k16]);
            #pragma unroll
            for (int mi = 0; mi < 2; mi++)
                #pragma unroll
                for (int nj = 0; nj < 4; nj++)
                    mma16816(acc[mi][nj], a[mi][0], a[mi][1], a[mi][2], a[mi][3],
                             b[nj >> 1][nj & 1], b[nj >> 1][(nj & 1) + 2]);
        }
    }

    #pragma unroll
    for (int mi = 0; mi < 2; mi++) {
        const size_t r0 = m0 + wm * 32 + mi * 16 + (lane >> 2);
        const size_t r1 = r0 + 8;
        const float i0 = rinv[r0];
        const float i1 = rinv[r1];
        #pragma unroll
        for (int nj = 0; nj < 4; nj++) {
            const size_t col = n0 + wn * 32 + nj * 8 + (lane & 3) * 2;
            float* c = acc[mi][nj];
            *reinterpret_cast<float2*>(&C[r0 * (size_t)N + col]) =
                make_float2(c[0] * i0, c[1] * i0);
            *reinterpret_cast<float2*>(&C[r1 * (size_t)N + col]) =
                make_float2(c[2] * i1, c[3] * i1);
        }
    }
}

// ---------------- row sums of P -> reciprocal --------------------------------
__global__ __launch_bounds__(256)
void rowsum_recip(const __half* __restrict__ P, float* __restrict__ rinv, int cols) {
    __shared__ float red[256];
    const int row = blockIdx.x;
    const int tid = threadIdx.x;
    const __half2* p = reinterpret_cast<const __half2*>(P + (size_t)row * cols);
    float s = 0.0f;
    for (int j = tid; j < cols / 2; j += 256) {
        float2 v = __half22float2(p[j]);
        s += v.x + v.y;
    }
    red[tid] = s;
    __syncthreads();
    #pragma unroll
    for (int st = 128; st > 0; st >>= 1) {
        if (tid < st) red[tid] += red[tid + st];
        __syncthreads();
    }
    if (tid == 0) rinv[row] = 1.0f / red[0];
}

// ---------------- launch ------------------------------------------------------
extern "C" void kernel_launch(void* const* d_in, const int* in_sizes, int n_in,
                              void* d_out, int out_size) {
    const float* q = (const float*)d_in[0];   // (4096, 4096)  Q[k][i]
    const float* k = (const float*)d_in[1];   // (4096, 8192)  K[k][j]
    const float* v = (const float*)d_in[2];   // (4096, 8192)  V[v][j]
    float* out = (float*)d_out;               // (4096, 4096)  out[i][v]

    __half *pQh, *pKh, *pVc, *pP;
    float* pRinv;
    cudaGetSymbolAddress((void**)&pQh,   g_Qh);
    cudaGetSymbolAddress((void**)&pKh,   g_Kh);
    cudaGetSymbolAddress((void**)&pVc,   g_Vc);
    cudaGetSymbolAddress((void**)&pP,    g_P);
    cudaGetSymbolAddress((void**)&pRinv, g_rinv);

    cudaFuncSetAttribute(gemm1_mma, cudaFuncAttributeMaxDynamicSharedMemorySize, SMEM1_SZ);
    cudaFuncSetAttribute(gemm2_mma, cudaFuncAttributeMaxDynamicSharedMemorySize, SMEM2_SZ);

    // straight converts (no transposes needed anymore)
    {
        size_t n = (size_t)NDIM * QDIM;
        convert_f2h<<<(unsigned)(n / 4 / 256), 256>>>(q, pQh, n);
    }
    {
        size_t n = (size_t)NDIM * MDIM;
        convert_f2h<<<(unsigned)(n / 4 / 256), 256>>>(k, pKh, n);
    }
    {
        size_t n = (size_t)VDIM * MDIM;
        convert_f2h<<<(unsigned)(n / 4 / 256), 256>>>(v, pVc, n);
    }

    // GEMM1 (trans-load) + fused exp: P[i][j] = exp(scale * sum_k Qh[k][i] Kh[k][j])
    gemm1_mma<<<dim3(MDIM / BN1, QDIM / BM1), 512, SMEM1_SZ>>>(
        pQh, pKh, pP, QDIM, MDIM, NDIM);

    // row sums -> reciprocals
    rowsum_recip<<<QDIM, 256>>>(pP, pRinv, MDIM);

    // GEMM2 + fused normalize: out[i][v] = rinv[i] * sum_j P[i][j] Vc[v][j]
    gemm2_mma<<<dim3(VDIM / BN2, QDIM / BM2), 256, SMEM2_SZ>>>(
        pP, pVc, out, QDIM, VDIM, MDIM, pRinv);
}

// round 11
// speedup vs baseline: 1.0011x; 1.0011x over previous
#include <cuda_runtime.h>
#include <cuda_fp16.h>
#include <cstdint>

#define QDIM 4096   // q_dim (output rows i)
#define NDIM 4096   // contraction of GEMM1 (n)
#define MDIM 8192   // softmax dim / contraction of GEMM2 (j)
#define VDIM 4096   // v_dim (output cols v)

// ---------------- scratch (static device globals) ---------------------------
__device__ __half g_Qt[(size_t)QDIM * NDIM];   // Qt[i][n] = Q[n][i]
__device__ __half g_Kt[(size_t)MDIM * NDIM];   // Kt[j][n] = K[n][j]
__device__ __half g_Vc[(size_t)VDIM * MDIM];   // Vc[v][j] = V[v][j]
__device__ __half g_P [(size_t)QDIM * MDIM];   // exp(s) UNNORMALIZED fp16
__device__ float  g_rinv[QDIM];                // 1 / row sums
__device__ float  g_part[2][(size_t)QDIM * VDIM];  // split-K partial sums

// ---------------- helpers ----------------------------------------------------
__device__ __forceinline__ uint32_t smem_u32(const void* p) {
    uint32_t a;
    asm("{ .reg .u64 t; cvta.to.shared.u64 t, %1; cvt.u32.u64 %0, t; }" : "=r"(a) : "l"(p));
    return a;
}
__device__ __forceinline__ void cp16(uint32_t dst, const void* src) {
    asm volatile("cp.async.cg.shared.global [%0], [%1], 16;" :: "r"(dst), "l"(src));
}
__device__ __forceinline__ void ldsm4(uint32_t& r0, uint32_t& r1, uint32_t& r2, uint32_t& r3,
                                      uint32_t addr) {
    asm volatile("ldmatrix.sync.aligned.m8n8.x4.shared.b16 {%0,%1,%2,%3}, [%4];"
                 : "=r"(r0), "=r"(r1), "=r"(r2), "=r"(r3) : "r"(addr));
}
__device__ __forceinline__ void mma16816(float* d, uint32_t a0, uint32_t a1, uint32_t a2,
                                         uint32_t a3, uint32_t b0, uint32_t b1) {
    asm volatile(
        "mma.sync.aligned.m16n8k16.row.col.f32.f16.f16.f32 "
        "{%0,%1,%2,%3}, {%4,%5,%6,%7}, {%8,%9}, {%0,%1,%2,%3};"
        : "+f"(d[0]), "+f"(d[1]), "+f"(d[2]), "+f"(d[3])
        : "r"(a0), "r"(a1), "r"(a2), "r"(a3), "r"(b0), "r"(b1));
}

// ---------------- preprocessing (known-good versions) -------------------------
__global__ void transpose_f2h(const float* __restrict__ in, __half* __restrict__ out,
                              int rows, int cols) {
    __shared__ float tile[32][33];
    int c0 = blockIdx.x * 32, r0 = blockIdx.y * 32;
    int tx = threadIdx.x, ty = threadIdx.y;
    #pragma unroll
    for (int i = ty; i < 32; i += 8)
        tile[i][tx] = in[(size_t)(r0 + i) * cols + (c0 + tx)];
    __syncthreads();
    #pragma unroll
    for (int i = ty; i < 32; i += 8)
        out[(size_t)(c0 + i) * rows + (r0 + tx)] = __float2half(tile[tx][i]);
}

__global__ void convert_f2h(const float* __restrict__ in, __half* __restrict__ out, size_t n) {
    size_t i = ((size_t)blockIdx.x * blockDim.x + threadIdx.x) * 4;
    if (i + 3 < n) {
        float4 v = *reinterpret_cast<const float4*>(in + i);
        *reinterpret_cast<__half2*>(out + i)     = __floats2half2_rn(v.x, v.y);
        *reinterpret_cast<__half2*>(out + i + 2) = __floats2half2_rn(v.z, v.w);
    }
}

// =============================================================================
// GEMM1 (R8/R9 config, measured 718us): 512 thr, 128x256, warp 32x64, 4 stages.
// C = exp(scale*acc) fp16
// =============================================================================
#define BM1 128
#define BN1 256
#define BKC 64
#define STAGES1 4
#define STG1_BYTES ((BM1 + BN1) * 128)        // 48 KB
#define SMEM1_SZ (STAGES1 * STG1_BYTES)       // 192 KB

__global__ __launch_bounds__(512, 1)
void gemm1_mma(const __half* __restrict__ A, const __half* __restrict__ B,
               __half* __restrict__ C, int M, int N, int K) {
    extern __shared__ char smem[];
    const uint32_t sb = smem_u32(smem);
    const int tid = threadIdx.x;
    const int wid = tid >> 5;
    const int lane = tid & 31;
    const int wm = wid & 3;            // 4 warps over M -> 32 rows
    const int wn = wid >> 2;           // 4 warps over N -> 64 cols
    const size_t m0 = (size_t)blockIdx.y * BM1;
    const size_t n0 = (size_t)blockIdx.x * BN1;
    const int nk = K / BKC;

    const int ldrow = tid >> 3;
    const int ldc16 = tid & 7;
    const uint32_t swz_st = ((uint32_t)ldc16 ^ ((uint32_t)ldrow & 7)) << 4;

    auto load_stage = [&](int c, int buf) {
        const uint32_t abase = sb + buf * STG1_BYTES;
        const uint32_t bbase = abase + BM1 * 128;
        const size_t k0 = (size_t)c * BKC;
        #pragma unroll
        for (int i = 0; i < 2; i++) {
            int row = ldrow + i * 64;
            cp16(abase + row * 128 + swz_st, A + (m0 + row) * (size_t)K + k0 + ldc16 * 8);
        }
        #pragma unroll
        for (int i = 0; i < 4; i++) {
            int row = ldrow + i * 64;
            cp16(bbase + row * 128 + swz_st, B + (n0 + row) * (size_t)K + k0 + ldc16 * 8);
        }
        asm volatile("cp.async.commit_group;" ::: "memory");
    };

    float acc[2][8][4];
    #pragma unroll
    for (int i = 0; i < 2; i++)
        #pragma unroll
        for (int j = 0; j < 8; j++)
            #pragma unroll
            for (int r = 0; r < 4; r++) acc[i][j][r] = 0.0f;

    #pragma unroll
    for (int s = 0; s < STAGES1 - 1; s++) load_stage(s, s);

    const uint32_t lrow = lane & 15;
    const uint32_t lhalf = lane >> 4;
    const uint32_t lswz = lane & 7;
    const uint32_t a_rowbyte = (wm * 32 + lrow) * 128;
    const uint32_t b_rowbyte = (wn * 64 + lrow) * 128;
    uint32_t coff[4];
    #pragma unroll
    for (int k16 = 0; k16 < 4; k16++)
        coff[k16] = (((uint32_t)k16 * 2 + lhalf) ^ lswz) << 4;

    for (int it = 0; it < nk; it++) {
        const int rem = nk - 1 - it;
        if (rem >= 2)      asm volatile("cp.async.wait_group 2;" ::: "memory");
        else if (rem == 1) asm volatile("cp.async.wait_group 1;" ::: "memory");
        else               asm volatile("cp.async.wait_group 0;" ::: "memory");
        __syncthreads();
        if (it + STAGES1 - 1 < nk) load_stage(it + STAGES1 - 1, (it + STAGES1 - 1) % STAGES1);

        const uint32_t abase = sb + (it % STAGES1) * STG1_BYTES;
        const uint32_t bbase = abase + BM1 * 128;

        #pragma unroll
        for (int k16 = 0; k16 < 4; k16++) {
            uint32_t a[2][4], b[4][4];
            #pragma unroll
            for (int mi = 0; mi < 2; mi++)
                ldsm4(a[mi][0], a[mi][1], a[mi][2], a[mi][3],
                      abase + a_rowbyte + mi * 2048 + coff[k16]);
            #pragma unroll
            for (int ni = 0; ni < 4; ni++)
                ldsm4(b[ni][0], b[ni][1], b[ni][2], b[ni][3],
                      bbase + b_rowbyte + ni * 2048 + coff[k16]);
            #pragma unroll
            for (int mi = 0; mi < 2; mi++)
                #pragma unroll
                for (int nj = 0; nj < 8; nj++)
                    mma16816(acc[mi][nj], a[mi][0], a[mi][1], a[mi][2], a[mi][3],
                             b[nj >> 1][nj & 1], b[nj >> 1][(nj & 1) + 2]);
        }
    }

    const float scale = 0.015625f;     // 1/sqrt(4096)
    #pragma unroll
    for (int mi = 0; mi < 2; mi++) {
        const size_t r0 = m0 + wm * 32 + mi * 16 + (lane >> 2);
        const size_t r1 = r0 + 8;
        #pragma unroll
        for (int nj = 0; nj < 8; nj++) {
            const size_t col = n0 + wn * 64 + nj * 8 + (lane & 3) * 2;
            float* c = acc[mi][nj];
            *reinterpret_cast<__half2*>(&C[r0 * (size_t)N + col]) =
                __floats2half2_rn(__expf(c[0] * scale), __expf(c[1] * scale));
            *reinterpret_cast<__half2*>(&C[r1 * (size_t)N + col]) =
                __floats2half2_rn(__expf(c[2] * scale), __expf(c[3] * scale));
        }
    }
}

// =============================================================================
// GEMM2 split-K=2: 512 thr, tile 128x128, warp 32x32 (4x4), 3 stages, 2 CTAs/SM.
// blockIdx.z selects K-half; raw partial sums -> Cpart (no rinv; deterministic).
// grid 2048 CTAs -> 6.92 waves.
// =============================================================================
#define BM2 128
#define BN2 128
#define STAGES2 3
#define STG2_BYTES ((BM2 + BN2) * 128)        // 32 KB
#define SMEM2_SZ (STAGES2 * STG2_BYTES)       // 96 KB

__global__ __launch_bounds__(512, 2)
void gemm2_mma(const __half* __restrict__ A, const __half* __restrict__ B,
               float* __restrict__ Cpart, int M, int N, int K) {
    extern __shared__ char smem[];
    const uint32_t sb = smem_u32(smem);
    const int tid = threadIdx.x;
    const int wid = tid >> 5;          // 0..15
    const int lane = tid & 31;
    const int wm = wid & 3;            // 4 warps over M -> 32 rows
    const int wn = wid >> 2;           // 4 warps over N -> 32 cols
    const size_t m0 = (size_t)blockIdx.y * BM2;
    const size_t n0 = (size_t)blockIdx.x * BN2;
    const int khalf = K >> 1;
    const size_t kb = (size_t)blockIdx.z * khalf;      // K-half base
    float* C = Cpart + (size_t)blockIdx.z * (size_t)M * N;
    const int nk = khalf / BKC;

    const int ldrow = tid >> 3;        // 0..63
    const int ldc16 = tid & 7;
    const uint32_t swz_st = ((uint32_t)ldc16 ^ ((uint32_t)ldrow & 7)) << 4;

    auto load_stage = [&](int c, int buf) {
        const uint32_t abase = sb + buf * STG2_BYTES;
        const uint32_t bbase = abase + BM2 * 128;
        const size_t k0 = kb + (size_t)c * BKC;
        #pragma unroll
        for (int i = 0; i < 2; i++) {                  // A: 128 rows
            int row = ldrow + i * 64;
            cp16(abase + row * 128 + swz_st, A + (m0 + row) * (size_t)K + k0 + ldc16 * 8);
        }
        #pragma unroll
        for (int i = 0; i < 2; i++) {                  // B: 128 rows
            int row = ldrow + i * 64;
            cp16(bbase + row * 128 + swz_st, B + (n0 + row) * (size_t)K + k0 + ldc16 * 8);
        }
        asm volatile("cp.async.commit_group;" ::: "memory");
    };

    float acc[2][4][4];
    #pragma unroll
    for (int i = 0; i < 2; i++)
        #pragma unroll
        for (int j = 0; j < 4; j++)
            #pragma unroll
            for (int r = 0; r < 4; r++) acc[i][j][r] = 0.0f;

    #pragma unroll
    for (int s = 0; s < STAGES2 - 1; s++) load_stage(s, s);

    const uint32_t lrow = lane & 15;
    const uint32_t lhalf = lane >> 4;
    const uint32_t lswz = lane & 7;
    const uint32_t a_rowbyte = (wm * 32 + lrow) * 128;
    const uint32_t b_rowbyte = (wn * 32 + lrow) * 128;
    uint32_t coff[4];
    #pragma unroll
    for (int k16 = 0; k16 < 4; k16++)
        coff[k16] = (((uint32_t)k16 * 2 + lhalf) ^ lswz) << 4;

    for (int it = 0; it < nk; it++) {
        if (it + 1 < nk) asm volatile("cp.async.wait_group 1;" ::: "memory");
        else             asm volatile("cp.async.wait_group 0;" ::: "memory");
        __syncthreads();
        if (it + STAGES2 - 1 < nk) load_stage(it + STAGES2 - 1, (it + STAGES2 - 1) % STAGES2);

        const uint32_t abase = sb + (it % STAGES2) * STG2_BYTES;
        const uint32_t bbase = abase + BM2 * 128;

        #pragma unroll
        for (int k16 = 0; k16 < 4; k16++) {
            uint32_t a[2][4], b[2][4];
            #pragma unroll
            for (int mi = 0; mi < 2; mi++)
                ldsm4(a[mi][0], a[mi][1], a[mi][2], a[mi][3],
                      abase + a_rowbyte + mi * 2048 + coff[k16]);
            #pragma unroll
            for (int ni = 0; ni < 2; ni++)
                ldsm4(b[ni][0], b[ni][1], b[ni][2], b[ni][3],
                      bbase + b_rowbyte + ni * 2048 + coff[k16]);
            #pragma unroll
            for (int mi = 0; mi < 2; mi++)
                #pragma unroll
                for (int nj = 0; nj < 4; nj++)
                    mma16816(acc[mi][nj], a[mi][0], a[mi][1], a[mi][2], a[mi][3],
                             b[nj >> 1][nj & 1], b[nj >> 1][(nj & 1) + 2]);
        }
    }

    #pragma unroll
    for (int mi = 0; mi < 2; mi++) {
        const size_t r0 = m0 + wm * 32 + mi * 16 + (lane >> 2);
        const size_t r1 = r0 + 8;
        #pragma unroll
        for (int nj = 0; nj < 4; nj++) {
            const size_t col = n0 + wn * 32 + nj * 8 + (lane & 3) * 2;
            float* c = acc[mi][nj];
            *reinterpret_cast<float2*>(&C[r0 * (size_t)N + col]) = make_float2(c[0], c[1]);
            *reinterpret_cast<float2*>(&C[r1 * (size_t)N + col]) = make_float2(c[2], c[3]);
        }
    }
}

// ---------------- finalize: out = rinv[row] * (p0 + p1) ----------------------
__global__ __launch_bounds__(256)
void finalize_out(const float* __restrict__ p0, const float* __restrict__ p1,
                  const float* __restrict__ rinv, float* __restrict__ out, int cols) {
    const size_t i = ((size_t)blockIdx.x * 256 + threadIdx.x) * 4;
    const int row = (int)(i / cols);
    const float r = rinv[row];
    float4 a = *reinterpret_cast<const float4*>(p0 + i);
    float4 b = *reinterpret_cast<const float4*>(p1 + i);
    float4 o;
    o.x = (a.x + b.x) * r;
    o.y = (a.y + b.y) * r;
    o.z = (a.z + b.z) * r;
    o.w = (a.w + b.w) * r;
    *reinterpret_cast<float4*>(out + i) = o;
}

// ---------------- row sums of P -> reciprocal --------------------------------
__global__ __launch_bounds__(256)
void rowsum_recip(const __half* __restrict__ P, float* __restrict__ rinv, int cols) {
    __shared__ float red[256];
    const int row = blockIdx.x;
    const int tid = threadIdx.x;
    const __half2* p = reinterpret_cast<const __half2*>(P + (size_t)row * cols);
    float s = 0.0f;
    for (int j = tid; j < cols / 2; j += 256) {
        float2 v = __half22float2(p[j]);
        s += v.x + v.y;
    }
    red[tid] = s;
    __syncthreads();
    #pragma unroll
    for (int st = 128; st > 0; st >>= 1) {
        if (tid < st) red[tid] += red[tid + st];
        __syncthreads();
    }
    if (tid == 0) rinv[row] = 1.0f / red[0];
}

// ---------------- launch ------------------------------------------------------
extern "C" void kernel_launch(void* const* d_in, const int* in_sizes, int n_in,
                              void* d_out, int out_size) {
    const float* q = (const float*)d_in[0];   // (4096, 4096)  Q[n][i]
    const float* k = (const float*)d_in[1];   // (4096, 8192)  K[n][j]
    const float* v = (const float*)d_in[2];   // (4096, 8192)  V[v][j]
    float* out = (float*)d_out;               // (4096, 4096)  out[i][v]

    __half *pQt, *pKt, *pVc, *pP;
    float *pRinv, *pPart;
    cudaGetSymbolAddress((void**)&pQt,   g_Qt);
    cudaGetSymbolAddress((void**)&pKt,   g_Kt);
    cudaGetSymbolAddress((void**)&pVc,   g_Vc);
    cudaGetSymbolAddress((void**)&pP,    g_P);
    cudaGetSymbolAddress((void**)&pRinv, g_rinv);
    cudaGetSymbolAddress((void**)&pPart, g_part);

    cudaFuncSetAttribute(gemm1_mma, cudaFuncAttributeMaxDynamicSharedMemorySize, SMEM1_SZ);
    cudaFuncSetAttribute(gemm2_mma, cudaFuncAttributeMaxDynamicSharedMemorySize, SMEM2_SZ);

    dim3 tb(32, 8);
    // Qt[i][n] = Q[n][i]
    transpose_f2h<<<dim3(QDIM / 32, NDIM / 32), tb>>>(q, pQt, NDIM, QDIM);
    // Kt[j][n] = K[n][j]
    transpose_f2h<<<dim3(MDIM / 32, NDIM / 32), tb>>>(k, pKt, NDIM, MDIM);
    // Vc straight convert
    {
        size_t n = (size_t)VDIM * MDIM;
        convert_f2h<<<(unsigned)(n / 4 / 256), 256>>>(v, pVc, n);
    }

    // GEMM1 + fused exp: P[i][j] = exp(scale * sum_n Qt[i][n] Kt[j][n])
    gemm1_mma<<<dim3(MDIM / BN1, QDIM / BM1), 512, SMEM1_SZ>>>(
        pQt, pKt, pP, QDIM, MDIM, NDIM);

    // row sums -> reciprocals
    rowsum_recip<<<QDIM, 256>>>(pP, pRinv, MDIM);

    // GEMM2 split-K=2: partial sums (raw, no rinv)
    gemm2_mma<<<dim3(VDIM / BN2, QDIM / BM2, 2), 512, SMEM2_SZ>>>(
        pP, pVc, pPart, QDIM, VDIM, MDIM);

    // finalize: out = rinv * (p0 + p1)
    {
        size_t n = (size_t)QDIM * VDIM;
        finalize_out<<<(unsigned)(n / 4 / 256), 256>>>(
            pPart, pPart + n, pRinv, out, VDIM);
    }
}

// round 12
// speedup vs baseline: 1.0656x; 1.0644x over previous
#include <cuda_runtime.h>
#include <cuda_fp16.h>
#include <cstdint>

#define QDIM 4096   // q_dim (output rows i)
#define NDIM 4096   // contraction of GEMM1 (n)
#define MDIM 8192   // softmax dim / contraction of GEMM2 (j)
#define VDIM 4096   // v_dim (output cols v)
#define GX1  (MDIM / 256)   // GEMM1 grid.x = 32 partials per row

// ---------------- scratch (static device globals) ---------------------------
__device__ __half g_Qt[(size_t)QDIM * NDIM];   // Qt[i][n] = Q[n][i]
__device__ __half g_Kt[(size_t)MDIM * NDIM];   // Kt[j][n] = K[n][j]
__device__ __half g_Vc[(size_t)VDIM * MDIM];   // Vc[v][j] = V[v][j]
__device__ __half g_P [(size_t)QDIM * MDIM];   // exp(s) UNNORMALIZED fp16
__device__ float  g_psum[(size_t)QDIM * GX1];  // per-CTA partial row sums
__device__ float  g_rinv[QDIM];                // 1 / row sums

// ---------------- helpers ----------------------------------------------------
__device__ __forceinline__ uint32_t smem_u32(const void* p) {
    uint32_t a;
    asm("{ .reg .u64 t; cvta.to.shared.u64 t, %1; cvt.u32.u64 %0, t; }" : "=r"(a) : "l"(p));
    return a;
}
__device__ __forceinline__ void cp16(uint32_t dst, const void* src) {
    asm volatile("cp.async.cg.shared.global [%0], [%1], 16;" :: "r"(dst), "l"(src));
}
__device__ __forceinline__ void ldsm4(uint32_t& r0, uint32_t& r1, uint32_t& r2, uint32_t& r3,
                                      uint32_t addr) {
    asm volatile("ldmatrix.sync.aligned.m8n8.x4.shared.b16 {%0,%1,%2,%3}, [%4];"
                 : "=r"(r0), "=r"(r1), "=r"(r2), "=r"(r3) : "r"(addr));
}
__device__ __forceinline__ void mma16816(float* d, uint32_t a0, uint32_t a1, uint32_t a2,
                                         uint32_t a3, uint32_t b0, uint32_t b1) {
    asm volatile(
        "mma.sync.aligned.m16n8k16.row.col.f32.f16.f16.f32 "
        "{%0,%1,%2,%3}, {%4,%5,%6,%7}, {%8,%9}, {%0,%1,%2,%3};"
        : "+f"(d[0]), "+f"(d[1]), "+f"(d[2]), "+f"(d[3])
        : "r"(a0), "r"(a1), "r"(a2), "r"(a3), "r"(b0), "r"(b1));
}

// ---------------- preprocessing ----------------------------------------------
// Vectorized 64x64 transpose: out[c][r] = (half) in[r][c].
// float4 global loads; 16B (8 x half) global stores.
__global__ __launch_bounds__(256)
void transpose_f2h_v(const float* __restrict__ in, __half* __restrict__ out,
                     int rows, int cols) {
    __shared__ float tile[64][65];
    const int c0 = blockIdx.x * 64, r0 = blockIdx.y * 64;
    const int tid = threadIdx.x;
    const int lr = tid >> 4, lc = tid & 15;       // load: row, float4-chunk
    #pragma unroll
    for (int i = 0; i < 4; i++) {
        int r = lr + i * 16;
        float4 v = *reinterpret_cast<const float4*>(&in[(size_t)(r0 + r) * cols + c0 + lc * 4]);
        tile[r][lc * 4 + 0] = v.x; tile[r][lc * 4 + 1] = v.y;
        tile[r][lc * 4 + 2] = v.z; tile[r][lc * 4 + 3] = v.w;
    }
    __syncthreads();
    const int oc = tid >> 3, och = tid & 7;       // store: out-row (c), 8-half chunk
    #pragma unroll
    for (int i = 0; i < 2; i++) {
        int c = oc + i * 32;
        __half h[8];
        #pragma unroll
        for (int j = 0; j < 8; j++) h[j] = __float2half(tile[och * 8 + j][c]);
        *reinterpret_cast<uint4*>(&out[(size_t)(c0 + c) * rows + r0 + och * 8]) =
            *reinterpret_cast<uint4*>(h);
    }
}

__global__ void convert_f2h(const float* __restrict__ in, __half* __restrict__ out, size_t n) {
    size_t i = ((size_t)blockIdx.x * blockDim.x + threadIdx.x) * 4;
    if (i + 3 < n) {
        float4 v = *reinterpret_cast<const float4*>(in + i);
        *reinterpret_cast<__half2*>(out + i)     = __floats2half2_rn(v.x, v.y);
        *reinterpret_cast<__half2*>(out + i + 2) = __floats2half2_rn(v.z, v.w);
    }
}

// =============================================================================
// GEMM1 (best measured 718us): 512 thr, 128x256, warp 32x64, 4 stages.
// C = exp(scale*acc) fp16 + fused per-CTA partial row sums -> psum.
// =============================================================================
#define BM1 128
#define BN1 256
#define BKC 64
#define STAGES1 4
#define STG1_BYTES ((BM1 + BN1) * 128)        // 48 KB
#define SMEM1_SZ (STAGES1 * STG1_BYTES)       // 192 KB

__global__ __launch_bounds__(512, 1)
void gemm1_mma(const __half* __restrict__ A, const __half* __restrict__ B,
               __half* __restrict__ C, float* __restrict__ psum,
               int M, int N, int K) {
    extern __shared__ char smem[];
    const uint32_t sb = smem_u32(smem);
    const int tid = threadIdx.x;
    const int wid = tid >> 5;
    const int lane = tid & 31;
    const int wm = wid & 3;            // 4 warps over M -> 32 rows
    const int wn = wid >> 2;           // 4 warps over N -> 64 cols
    const size_t m0 = (size_t)blockIdx.y * BM1;
    const size_t n0 = (size_t)blockIdx.x * BN1;
    const int nk = K / BKC;

    const int ldrow = tid >> 3;
    const int ldc16 = tid & 7;
    const uint32_t swz_st = ((uint32_t)ldc16 ^ ((uint32_t)ldrow & 7)) << 4;

    auto load_stage = [&](int c, int buf) {
        const uint32_t abase = sb + buf * STG1_BYTES;
        const uint32_t bbase = abase + BM1 * 128;
        const size_t k0 = (size_t)c * BKC;
        #pragma unroll
        for (int i = 0; i < 2; i++) {
            int row = ldrow + i * 64;
            cp16(abase + row * 128 + swz_st, A + (m0 + row) * (size_t)K + k0 + ldc16 * 8);
        }
        #pragma unroll
        for (int i = 0; i < 4; i++) {
            int row = ldrow + i * 64;
            cp16(bbase + row * 128 + swz_st, B + (n0 + row) * (size_t)K + k0 + ldc16 * 8);
        }
        asm volatile("cp.async.commit_group;" ::: "memory");
    };

    float acc[2][8][4];
    #pragma unroll
    for (int i = 0; i < 2; i++)
        #pragma unroll
        for (int j = 0; j < 8; j++)
            #pragma unroll
            for (int r = 0; r < 4; r++) acc[i][j][r] = 0.0f;

    #pragma unroll
    for (int s = 0; s < STAGES1 - 1; s++) load_stage(s, s);

    const uint32_t lrow = lane & 15;
    const uint32_t lhalf = lane >> 4;
    const uint32_t lswz = lane & 7;
    const uint32_t a_rowbyte = (wm * 32 + lrow) * 128;
    const uint32_t b_rowbyte = (wn * 64 + lrow) * 128;
    uint32_t coff[4];
    #pragma unroll
    for (int k16 = 0; k16 < 4; k16++)
        coff[k16] = (((uint32_t)k16 * 2 + lhalf) ^ lswz) << 4;

    for (int it = 0; it < nk; it++) {
        const int rem = nk - 1 - it;
        if (rem >= 2)      asm volatile("cp.async.wait_group 2;" ::: "memory");
        else if (rem == 1) asm volatile("cp.async.wait_group 1;" ::: "memory");
        else               asm volatile("cp.async.wait_group 0;" ::: "memory");
        __syncthreads();
        if (it + STAGES1 - 1 < nk) load_stage(it + STAGES1 - 1, (it + STAGES1 - 1) % STAGES1);

        const uint32_t abase = sb + (it % STAGES1) * STG1_BYTES;
        const uint32_t bbase = abase + BM1 * 128;

        #pragma unroll
        for (int k16 = 0; k16 < 4; k16++) {
            uint32_t a[2][4], b[4][4];
            #pragma unroll
            for (int mi = 0; mi < 2; mi++)
                ldsm4(a[mi][0], a[mi][1], a[mi][2], a[mi][3],
                      abase + a_rowbyte + mi * 2048 + coff[k16]);
            #pragma unroll
            for (int ni = 0; ni < 4; ni++)
                ldsm4(b[ni][0], b[ni][1], b[ni][2], b[ni][3],
                      bbase + b_rowbyte + ni * 2048 + coff[k16]);
            #pragma unroll
            for (int mi = 0; mi < 2; mi++)
                #pragma unroll
                for (int nj = 0; nj < 8; nj++)
                    mma16816(acc[mi][nj], a[mi][0], a[mi][1], a[mi][2], a[mi][3],
                             b[nj >> 1][nj & 1], b[nj >> 1][(nj & 1) + 2]);
        }
    }

    // ---- epilogue: store exp, accumulate per-row partial sums ---------------
    const float scale = 0.015625f;     // 1/sqrt(4096)
    float s0[2], s1[2];
    #pragma unroll
    for (int mi = 0; mi < 2; mi++) { s0[mi] = 0.0f; s1[mi] = 0.0f; }
    #pragma unroll
    for (int mi = 0; mi < 2; mi++) {
        const size_t r0 = m0 + wm * 32 + mi * 16 + (lane >> 2);
        const size_t r1 = r0 + 8;
        #pragma unroll
        for (int nj = 0; nj < 8; nj++) {
            const size_t col = n0 + wn * 64 + nj * 8 + (lane & 3) * 2;
            float* c = acc[mi][nj];
            float e0 = __expf(c[0] * scale), e1 = __expf(c[1] * scale);
            float e2 = __expf(c[2] * scale), e3 = __expf(c[3] * scale);
            *reinterpret_cast<__half2*>(&C[r0 * (size_t)N + col]) = __floats2half2_rn(e0, e1);
            *reinterpret_cast<__half2*>(&C[r1 * (size_t)N + col]) = __floats2half2_rn(e2, e3);
            s0[mi] += e0 + e1;
            s1[mi] += e2 + e3;
        }
    }
    // reduce across the 4 lanes holding the same row (lane ^ 1, lane ^ 2)
    float* red = reinterpret_cast<float*>(smem);   // 128 rows x 4 warps = 2 KB
    __syncthreads();                                // all mainloop smem reads done
    #pragma unroll
    for (int mi = 0; mi < 2; mi++) {
        float a = s0[mi], b = s1[mi];
        a += __shfl_xor_sync(0xFFFFFFFFu, a, 1);
        a += __shfl_xor_sync(0xFFFFFFFFu, a, 2);
        b += __shfl_xor_sync(0xFFFFFFFFu, b, 1);
        b += __shfl_xor_sync(0xFFFFFFFFu, b, 2);
        if ((lane & 3) == 0) {
            int rl = wm * 32 + mi * 16 + (lane >> 2);
            red[rl * 4 + wn] = a;
            red[(rl + 8) * 4 + wn] = b;
        }
    }
    __syncthreads();
    if (tid < BM1) {
        float s = red[tid * 4] + red[tid * 4 + 1] + red[tid * 4 + 2] + red[tid * 4 + 3];
        psum[(m0 + tid) * GX1 + blockIdx.x] = s;
    }
}

// ---------------- reduce psum partials -> rinv -------------------------------
__global__ __launch_bounds__(256)
void rowsum_recip2(const float* __restrict__ psum, float* __restrict__ rinv) {
    const int row = blockIdx.x * 8 + (threadIdx.x >> 5);
    const int lane = threadIdx.x & 31;
    float v = psum[(size_t)row * GX1 + lane];
    #pragma unroll
    for (int o = 16; o > 0; o >>= 1) v += __shfl_xor_sync(0xFFFFFFFFu, v, o);
    if (lane == 0) rinv[row] = 1.0f / v;
}

// =============================================================================
// GEMM2 (R9 measured config): 512 thr, 128x128, warp 32x32, 3 stages.
// C = acc * rinv[row] fp32
// =============================================================================
#define BM2 128
#define BN2 128
#define STAGES2 3
#define STG2_BYTES ((BM2 + BN2) * 128)        // 32 KB
#define SMEM2_SZ (STAGES2 * STG2_BYTES)       // 96 KB

__global__ __launch_bounds__(512, 2)
void gemm2_mma(const __half* __restrict__ A, const __half* __restrict__ B,
               float* __restrict__ C, int M, int N, int K,
               const float* __restrict__ rinv) {
    extern __shared__ char smem[];
    const uint32_t sb = smem_u32(smem);
    const int tid = threadIdx.x;
    const int wid = tid >> 5;          // 0..15
    const int lane = tid & 31;
    const int wm = wid & 3;            // 4 warps over M -> 32 rows
    const int wn = wid >> 2;           // 4 warps over N -> 32 cols
    const size_t m0 = (size_t)blockIdx.y * BM2;
    const size_t n0 = (size_t)blockIdx.x * BN2;
    const int nk = K / BKC;

    const int ldrow = tid >> 3;        // 0..63
    const int ldc16 = tid & 7;
    const uint32_t swz_st = ((uint32_t)ldc16 ^ ((uint32_t)ldrow & 7)) << 4;

    auto load_stage = [&](int c, int buf) {
        const uint32_t abase = sb + buf * STG2_BYTES;
        const uint32_t bbase = abase + BM2 * 128;
        const size_t k0 = (size_t)c * BKC;
        #pragma unroll
        for (int i = 0; i < 2; i++) {
            int row = ldrow + i * 64;
            cp16(abase + row * 128 + swz_st, A + (m0 + row) * (size_t)K + k0 + ldc16 * 8);
        }
        #pragma unroll
        for (int i = 0; i < 2; i++) {
            int row = ldrow + i * 64;
            cp16(bbase + row * 128 + swz_st, B + (n0 + row) * (size_t)K + k0 + ldc16 * 8);
        }
        asm volatile("cp.async.commit_group;" ::: "memory");
    };

    float acc[2][4][4];
    #pragma unroll
    for (int i = 0; i < 2; i++)
        #pragma unroll
        for (int j = 0; j < 4; j++)
            #pragma unroll
            for (int r = 0; r < 4; r++) acc[i][j][r] = 0.0f;

    #pragma unroll
    for (int s = 0; s < STAGES2 - 1; s++) load_stage(s, s);

    const uint32_t lrow = lane & 15;
    const uint32_t lhalf = lane >> 4;
    const uint32_t lswz = lane & 7;
    const uint32_t a_rowbyte = (wm * 32 + lrow) * 128;
    const uint32_t b_rowbyte = (wn * 32 + lrow) * 128;
    uint32_t coff[4];
    #pragma unroll
    for (int k16 = 0; k16 < 4; k16++)
        coff[k16] = (((uint32_t)k16 * 2 + lhalf) ^ lswz) << 4;

    for (int it = 0; it < nk; it++) {
        if (it + 1 < nk) asm volatile("cp.async.wait_group 1;" ::: "memory");
        else             asm volatile("cp.async.wait_group 0;" ::: "memory");
        __syncthreads();
        if (it + STAGES2 - 1 < nk) load_stage(it + STAGES2 - 1, (it + STAGES2 - 1) % STAGES2);

        const uint32_t abase = sb + (it % STAGES2) * STG2_BYTES;
        const uint32_t bbase = abase + BM2 * 128;

        #pragma unroll
        for (int k16 = 0; k16 < 4; k16++) {
            uint32_t a[2][4], b[2][4];
            #pragma unroll
            for (int mi = 0; mi < 2; mi++)
                ldsm4(a[mi][0], a[mi][1], a[mi][2], a[mi][3],
                      abase + a_rowbyte + mi * 2048 + coff[k16]);
            #pragma unroll
            for (int ni = 0; ni < 2; ni++)
                ldsm4(b[ni][0], b[ni][1], b[ni][2], b[ni][3],
                      bbase + b_rowbyte + ni * 2048 + coff[k16]);
            #pragma unroll
            for (int mi = 0; mi < 2; mi++)
                #pragma unroll
                for (int nj = 0; nj < 4; nj++)
                    mma16816(acc[mi][nj], a[mi][0], a[mi][1], a[mi][2], a[mi][3],
                             b[nj >> 1][nj & 1], b[nj >> 1][(nj & 1) + 2]);
        }
    }

    #pragma unroll
    for (int mi = 0; mi < 2; mi++) {
        const size_t r0 = m0 + wm * 32 + mi * 16 + (lane >> 2);
        const size_t r1 = r0 + 8;
        const float i0 = rinv[r0];
        const float i1 = rinv[r1];
        #pragma unroll
        for (int nj = 0; nj < 4; nj++) {
            const size_t col = n0 + wn * 32 + nj * 8 + (lane & 3) * 2;
            float* c = acc[mi][nj];
            *reinterpret_cast<float2*>(&C[r0 * (size_t)N + col]) =
                make_float2(c[0] * i0, c[1] * i0);
            *reinterpret_cast<float2*>(&C[r1 * (size_t)N + col]) =
                make_float2(c[2] * i1, c[3] * i1);
        }
    }
}

// ---------------- launch ------------------------------------------------------
extern "C" void kernel_launch(void* const* d_in, const int* in_sizes, int n_in,
                              void* d_out, int out_size) {
    const float* q = (const float*)d_in[0];   // (4096, 4096)  Q[n][i]
    const float* k = (const float*)d_in[1];   // (4096, 8192)  K[n][j]
    const float* v = (const float*)d_in[2];   // (4096, 8192)  V[v][j]
    float* out = (float*)d_out;               // (4096, 4096)  out[i][v]

    __half *pQt, *pKt, *pVc, *pP;
    float *pPsum, *pRinv;
    cudaGetSymbolAddress((void**)&pQt,   g_Qt);
    cudaGetSymbolAddress((void**)&pKt,   g_Kt);
    cudaGetSymbolAddress((void**)&pVc,   g_Vc);
    cudaGetSymbolAddress((void**)&pP,    g_P);
    cudaGetSymbolAddress((void**)&pPsum, g_psum);
    cudaGetSymbolAddress((void**)&pRinv, g_rinv);

    cudaFuncSetAttribute(gemm1_mma, cudaFuncAttributeMaxDynamicSharedMemorySize, SMEM1_SZ);
    cudaFuncSetAttribute(gemm2_mma, cudaFuncAttributeMaxDynamicSharedMemorySize, SMEM2_SZ);

    // Qt[i][n] = Q[n][i] : in rows=NDIM, cols=QDIM
    transpose_f2h_v<<<dim3(QDIM / 64, NDIM / 64), 256>>>(q, pQt, NDIM, QDIM);
    // Kt[j][n] = K[n][j] : in rows=NDIM, cols=MDIM
    transpose_f2h_v<<<dim3(MDIM / 64, NDIM / 64), 256>>>(k, pKt, NDIM, MDIM);
    // Vc straight convert
    {
        size_t n = (size_t)VDIM * MDIM;
        convert_f2h<<<(unsigned)(n / 4 / 256), 256>>>(v, pVc, n);
    }

    // GEMM1 + fused exp + partial row sums
    gemm1_mma<<<dim3(MDIM / BN1, QDIM / BM1), 512, SMEM1_SZ>>>(
        pQt, pKt, pP, pPsum, QDIM, MDIM, NDIM);

    // reduce partials -> reciprocals
    rowsum_recip2<<<QDIM / 8, 256>>>(pPsum, pRinv);

    // GEMM2 + fused normalize
    gemm2_mma<<<dim3(VDIM / BN2, QDIM / BM2), 512, SMEM2_SZ>>>(
        pP, pVc, out, QDIM, VDIM, MDIM, pRinv);
}

// round 13
// speedup vs baseline: 1.0856x; 1.0188x over previous
#include <cuda_runtime.h>
#include <cuda_fp16.h>
#include <cstdint>

#define QDIM 4096   // q_dim (output rows i)
#define NDIM 4096   // contraction of GEMM1 (n)
#define MDIM 8192   // softmax dim / contraction of GEMM2 (j)
#define VDIM 4096   // v_dim (output cols v)
#define GX1  (MDIM / 256)   // GEMM1 grid.x = 32 partials per row

// ---------------- scratch (static device globals) ---------------------------
__device__ __half g_Qt[(size_t)QDIM * NDIM];   // Qt[i][n] = Q[n][i]
__device__ __half g_Kt[(size_t)MDIM * NDIM];   // Kt[j][n] = K[n][j]
__device__ __half g_Vc[(size_t)VDIM * MDIM];   // Vc[v][j] = V[v][j]
__device__ __half g_P [(size_t)QDIM * MDIM];   // exp(s) UNNORMALIZED fp16
__device__ float  g_psum[(size_t)QDIM * GX1];  // per-CTA partial row sums
__device__ float  g_rinv[QDIM];                // 1 / row sums

// ---------------- helpers ----------------------------------------------------
__device__ __forceinline__ uint32_t smem_u32(const void* p) {
    uint32_t a;
    asm("{ .reg .u64 t; cvta.to.shared.u64 t, %1; cvt.u32.u64 %0, t; }" : "=r"(a) : "l"(p));
    return a;
}
__device__ __forceinline__ void cp16(uint32_t dst, const void* src) {
    asm volatile("cp.async.cg.shared.global [%0], [%1], 16;" :: "r"(dst), "l"(src));
}
__device__ __forceinline__ void ldsm4(uint32_t& r0, uint32_t& r1, uint32_t& r2, uint32_t& r3,
                                      uint32_t addr) {
    asm volatile("ldmatrix.sync.aligned.m8n8.x4.shared.b16 {%0,%1,%2,%3}, [%4];"
                 : "=r"(r0), "=r"(r1), "=r"(r2), "=r"(r3) : "r"(addr));
}
__device__ __forceinline__ void mma16816(float* d, uint32_t a0, uint32_t a1, uint32_t a2,
                                         uint32_t a3, uint32_t b0, uint32_t b1) {
    asm volatile(
        "mma.sync.aligned.m16n8k16.row.col.f32.f16.f16.f32 "
        "{%0,%1,%2,%3}, {%4,%5,%6,%7}, {%8,%9}, {%0,%1,%2,%3};"
        : "+f"(d[0]), "+f"(d[1]), "+f"(d[2]), "+f"(d[3])
        : "r"(a0), "r"(a1), "r"(a2), "r"(a3), "r"(b0), "r"(b1));
}

// ---------------- preprocessing ----------------------------------------------
// Vectorized 64x64 transpose: out[c][r] = (half) in[r][c].
__global__ __launch_bounds__(256)
void transpose_f2h_v(const float* __restrict__ in, __half* __restrict__ out,
                     int rows, int cols) {
    __shared__ float tile[64][65];
    const int c0 = blockIdx.x * 64, r0 = blockIdx.y * 64;
    const int tid = threadIdx.x;
    const int lr = tid >> 4, lc = tid & 15;
    #pragma unroll
    for (int i = 0; i < 4; i++) {
        int r = lr + i * 16;
        float4 v = *reinterpret_cast<const float4*>(&in[(size_t)(r0 + r) * cols + c0 + lc * 4]);
        tile[r][lc * 4 + 0] = v.x; tile[r][lc * 4 + 1] = v.y;
        tile[r][lc * 4 + 2] = v.z; tile[r][lc * 4 + 3] = v.w;
    }
    __syncthreads();
    const int oc = tid >> 3, och = tid & 7;
    #pragma unroll
    for (int i = 0; i < 2; i++) {
        int c = oc + i * 32;
        __half h[8];
        #pragma unroll
        for (int j = 0; j < 8; j++) h[j] = __float2half(tile[och * 8 + j][c]);
        *reinterpret_cast<uint4*>(&out[(size_t)(c0 + c) * rows + r0 + och * 8]) =
            *reinterpret_cast<uint4*>(h);
    }
}

__global__ void convert_f2h(const float* __restrict__ in, __half* __restrict__ out, size_t n) {
    size_t i = ((size_t)blockIdx.x * blockDim.x + threadIdx.x) * 4;
    if (i + 3 < n) {
        float4 v = *reinterpret_cast<const float4*>(in + i);
        *reinterpret_cast<__half2*>(out + i)     = __floats2half2_rn(v.x, v.y);
        *reinterpret_cast<__half2*>(out + i + 2) = __floats2half2_rn(v.z, v.w);
    }
}

// =============================================================================
// GEMM1: 512 thr, 128x256, warp 32x64, 4 stages, mainloop unrolled by 4
// (compile-time smem buffer indices). C = exp(scale*acc) fp16 + fused psum.
// =============================================================================
#define BM1 128
#define BN1 256
#define BKC 64
#define STAGES1 4
#define STG1_BYTES ((BM1 + BN1) * 128)        // 48 KB
#define SMEM1_SZ (STAGES1 * STG1_BYTES)       // 192 KB

__global__ __launch_bounds__(512, 1)
void gemm1_mma(const __half* __restrict__ A, const __half* __restrict__ B,
               __half* __restrict__ C, float* __restrict__ psum,
               int M, int N, int K) {
    extern __shared__ char smem[];
    const uint32_t sb = smem_u32(smem);
    const int tid = threadIdx.x;
    const int wid = tid >> 5;
    const int lane = tid & 31;
    const int wm = wid & 3;            // 4 warps over M -> 32 rows
    const int wn = wid >> 2;           // 4 warps over N -> 64 cols
    const size_t m0 = (size_t)blockIdx.y * BM1;
    const size_t n0 = (size_t)blockIdx.x * BN1;
    const int nk = K / BKC;            // 64 (divisible by 4)

    const int ldrow = tid >> 3;
    const int ldc16 = tid & 7;
    const uint32_t swz_st = ((uint32_t)ldc16 ^ ((uint32_t)ldrow & 7)) << 4;

    auto load_stage = [&](int c, int buf) {
        const uint32_t abase = sb + buf * STG1_BYTES;
        const uint32_t bbase = abase + BM1 * 128;
        const size_t k0 = (size_t)c * BKC;
        #pragma unroll
        for (int i = 0; i < 2; i++) {
            int row = ldrow + i * 64;
            cp16(abase + row * 128 + swz_st, A + (m0 + row) * (size_t)K + k0 + ldc16 * 8);
        }
        #pragma unroll
        for (int i = 0; i < 4; i++) {
            int row = ldrow + i * 64;
            cp16(bbase + row * 128 + swz_st, B + (n0 + row) * (size_t)K + k0 + ldc16 * 8);
        }
        asm volatile("cp.async.commit_group;" ::: "memory");
    };

    float acc[2][8][4];
    #pragma unroll
    for (int i = 0; i < 2; i++)
        #pragma unroll
        for (int j = 0; j < 8; j++)
            #pragma unroll
            for (int r = 0; r < 4; r++) acc[i][j][r] = 0.0f;

    #pragma unroll
    for (int s = 0; s < STAGES1 - 1; s++) load_stage(s, s);

    const uint32_t lrow = lane & 15;
    const uint32_t lhalf = lane >> 4;
    const uint32_t lswz = lane & 7;
    const uint32_t a_rowbyte = (wm * 32 + lrow) * 128;
    const uint32_t b_rowbyte = (wn * 64 + lrow) * 128;
    uint32_t coff[4];
    #pragma unroll
    for (int k16 = 0; k16 < 4; k16++)
        coff[k16] = (((uint32_t)k16 * 2 + lhalf) ^ lswz) << 4;

    // mainloop unrolled by STAGES1: buffer indices are compile-time constants
    for (int it0 = 0; it0 < nk; it0 += STAGES1) {
        #pragma unroll
        for (int u = 0; u < STAGES1; u++) {
            const int it = it0 + u;
            const int rem = nk - 1 - it;
            if (rem >= 2)      asm volatile("cp.async.wait_group 2;" ::: "memory");
            else if (rem == 1) asm volatile("cp.async.wait_group 1;" ::: "memory");
            else               asm volatile("cp.async.wait_group 0;" ::: "memory");
            __syncthreads();
            if (it + STAGES1 - 1 < nk)
                load_stage(it + STAGES1 - 1, (u + STAGES1 - 1) % STAGES1);  // const buf

            const uint32_t abase = sb + u * STG1_BYTES;      // compile-time
            const uint32_t bbase = abase + BM1 * 128;

            #pragma unroll
            for (int k16 = 0; k16 < 4; k16++) {
                uint32_t a[2][4], b[4][4];
                #pragma unroll
                for (int mi = 0; mi < 2; mi++)
                    ldsm4(a[mi][0], a[mi][1], a[mi][2], a[mi][3],
                          abase + a_rowbyte + mi * 2048 + coff[k16]);
                #pragma unroll
                for (int ni = 0; ni < 4; ni++)
                    ldsm4(b[ni][0], b[ni][1], b[ni][2], b[ni][3],
                          bbase + b_rowbyte + ni * 2048 + coff[k16]);
                #pragma unroll
                for (int mi = 0; mi < 2; mi++)
                    #pragma unroll
                    for (int nj = 0; nj < 8; nj++)
                        mma16816(acc[mi][nj], a[mi][0], a[mi][1], a[mi][2], a[mi][3],
                                 b[nj >> 1][nj & 1], b[nj >> 1][(nj & 1) + 2]);
            }
        }
    }

    // ---- epilogue: store exp, accumulate per-row partial sums ---------------
    const float scale = 0.015625f;     // 1/sqrt(4096)
    float s0[2], s1[2];
    #pragma unroll
    for (int mi = 0; mi < 2; mi++) { s0[mi] = 0.0f; s1[mi] = 0.0f; }
    #pragma unroll
    for (int mi = 0; mi < 2; mi++) {
        const size_t r0 = m0 + wm * 32 + mi * 16 + (lane >> 2);
        const size_t r1 = r0 + 8;
        #pragma unroll
        for (int nj = 0; nj < 8; nj++) {
            const size_t col = n0 + wn * 64 + nj * 8 + (lane & 3) * 2;
            float* c = acc[mi][nj];
            float e0 = __expf(c[0] * scale), e1 = __expf(c[1] * scale);
            float e2 = __expf(c[2] * scale), e3 = __expf(c[3] * scale);
            *reinterpret_cast<__half2*>(&C[r0 * (size_t)N + col]) = __floats2half2_rn(e0, e1);
            *reinterpret_cast<__half2*>(&C[r1 * (size_t)N + col]) = __floats2half2_rn(e2, e3);
            s0[mi] += e0 + e1;
            s1[mi] += e2 + e3;
        }
    }
    float* red = reinterpret_cast<float*>(smem);
    __syncthreads();
    #pragma unroll
    for (int mi = 0; mi < 2; mi++) {
        float a = s0[mi], b = s1[mi];
        a += __shfl_xor_sync(0xFFFFFFFFu, a, 1);
        a += __shfl_xor_sync(0xFFFFFFFFu, a, 2);
        b += __shfl_xor_sync(0xFFFFFFFFu, b, 1);
        b += __shfl_xor_sync(0xFFFFFFFFu, b, 2);
        if ((lane & 3) == 0) {
            int rl = wm * 32 + mi * 16 + (lane >> 2);
            red[rl * 4 + wn] = a;
            red[(rl + 8) * 4 + wn] = b;
        }
    }
    __syncthreads();
    if (tid < BM1) {
        float s = red[tid * 4] + red[tid * 4 + 1] + red[tid * 4 + 2] + red[tid * 4 + 3];
        psum[(m0 + tid) * GX1 + blockIdx.x] = s;
    }
}

// ---------------- reduce psum partials -> rinv -------------------------------
__global__ __launch_bounds__(256)
void rowsum_recip2(const float* __restrict__ psum, float* __restrict__ rinv) {
    const int row = blockIdx.x * 8 + (threadIdx.x >> 5);
    const int lane = threadIdx.x & 31;
    float v = psum[(size_t)row * GX1 + lane];
    #pragma unroll
    for (int o = 16; o > 0; o >>= 1) v += __shfl_xor_sync(0xFFFFFFFFu, v, o);
    if (lane == 0) rinv[row] = 1.0f / v;
}

// =============================================================================
// GEMM2 (R9/R12 measured config, untouched): 512 thr, 128x128, warp 32x32,
// 3 stages, 2 CTAs/SM. C = acc * rinv[row] fp32
// =============================================================================
#define BM2 128
#define BN2 128
#define STAGES2 3
#define STG2_BYTES ((BM2 + BN2) * 128)        // 32 KB
#define SMEM2_SZ (STAGES2 * STG2_BYTES)       // 96 KB

__global__ __launch_bounds__(512, 2)
void gemm2_mma(const __half* __restrict__ A, const __half* __restrict__ B,
               float* __restrict__ C, int M, int N, int K,
               const float* __restrict__ rinv) {
    extern __shared__ char smem[];
    const uint32_t sb = smem_u32(smem);
    const int tid = threadIdx.x;
    const int wid = tid >> 5;          // 0..15
    const int lane = tid & 31;
    const int wm = wid & 3;            // 4 warps over M -> 32 rows
    const int wn = wid >> 2;           // 4 warps over N -> 32 cols
    const size_t m0 = (size_t)blockIdx.y * BM2;
    const size_t n0 = (size_t)blockIdx.x * BN2;
    const int nk = K / BKC;

    const int ldrow = tid >> 3;        // 0..63
    const int ldc16 = tid & 7;
    const uint32_t swz_st = ((uint32_t)ldc16 ^ ((uint32_t)ldrow & 7)) << 4;

    auto load_stage = [&](int c, int buf) {
        const uint32_t abase = sb + buf * STG2_BYTES;
        const uint32_t bbase = abase + BM2 * 128;
        const size_t k0 = (size_t)c * BKC;
        #pragma unroll
        for (int i = 0; i < 2; i++) {
            int row = ldrow + i * 64;
            cp16(abase + row * 128 + swz_st, A + (m0 + row) * (size_t)K + k0 + ldc16 * 8);
        }
        #pragma unroll
        for (int i = 0; i < 2; i++) {
            int row = ldrow + i * 64;
            cp16(bbase + row * 128 + swz_st, B + (n0 + row) * (size_t)K + k0 + ldc16 * 8);
        }
        asm volatile("cp.async.commit_group;" ::: "memory");
    };

    float acc[2][4][4];
    #pragma unroll
    for (int i = 0; i < 2; i++)
        #pragma unroll
        for (int j = 0; j < 4; j++)
            #pragma unroll
            for (int r = 0; r < 4; r++) acc[i][j][r] = 0.0f;

    #pragma unroll
    for (int s = 0; s < STAGES2 - 1; s++) load_stage(s, s);

    const uint32_t lrow = lane & 15;
    const uint32_t lhalf = lane >> 4;
    const uint32_t lswz = lane & 7;
    const uint32_t a_rowbyte = (wm * 32 + lrow) * 128;
    const uint32_t b_rowbyte = (wn * 32 + lrow) * 128;
    uint32_t coff[4];
    #pragma unroll
    for (int k16 = 0; k16 < 4; k16++)
        coff[k16] = (((uint32_t)k16 * 2 + lhalf) ^ lswz) << 4;

    for (int it = 0; it < nk; it++) {
        if (it + 1 < nk) asm volatile("cp.async.wait_group 1;" ::: "memory");
        else             asm volatile("cp.async.wait_group 0;" ::: "memory");
        __syncthreads();
        if (it + STAGES2 - 1 < nk) load_stage(it + STAGES2 - 1, (it + STAGES2 - 1) % STAGES2);

        const uint32_t abase = sb + (it % STAGES2) * STG2_BYTES;
        const uint32_t bbase = abase + BM2 * 128;

        #pragma unroll
        for (int k16 = 0; k16 < 4; k16++) {
            uint32_t a[2][4], b[2][4];
            #pragma unroll
            for (int mi = 0; mi < 2; mi++)
                ldsm4(a[mi][0], a[mi][1], a[mi][2], a[mi][3],
                      abase + a_rowbyte + mi * 2048 + coff[k16]);
            #pragma unroll
            for (int ni = 0; ni < 2; ni++)
                ldsm4(b[ni][0], b[ni][1], b[ni][2], b[ni][3],
                      bbase + b_rowbyte + ni * 2048 + coff[k16]);
            #pragma unroll
            for (int mi = 0; mi < 2; mi++)
                #pragma unroll
                for (int nj = 0; nj < 4; nj++)
                    mma16816(acc[mi][nj], a[mi][0], a[mi][1], a[mi][2], a[mi][3],
                             b[nj >> 1][nj & 1], b[nj >> 1][(nj & 1) + 2]);
        }
    }

    #pragma unroll
    for (int mi = 0; mi < 2; mi++) {
        const size_t r0 = m0 + wm * 32 + mi * 16 + (lane >> 2);
        const size_t r1 = r0 + 8;
        const float i0 = rinv[r0];
        const float i1 = rinv[r1];
        #pragma unroll
        for (int nj = 0; nj < 4; nj++) {
            const size_t col = n0 + wn * 32 + nj * 8 + (lane & 3) * 2;
            float* c = acc[mi][nj];
            *reinterpret_cast<float2*>(&C[r0 * (size_t)N + col]) =
                make_float2(c[0] * i0, c[1] * i0);
            *reinterpret_cast<float2*>(&C[r1 * (size_t)N + col]) =
                make_float2(c[2] * i1, c[3] * i1);
        }
    }
}

// ---------------- launch ------------------------------------------------------
extern "C" void kernel_launch(void* const* d_in, const int* in_sizes, int n_in,
                              void* d_out, int out_size) {
    const float* q = (const float*)d_in[0];   // (4096, 4096)  Q[n][i]
    const float* k = (const float*)d_in[1];   // (4096, 8192)  K[n][j]
    const float* v = (const float*)d_in[2];   // (4096, 8192)  V[v][j]
    float* out = (float*)d_out;               // (4096, 4096)  out[i][v]

    __half *pQt, *pKt, *pVc, *pP;
    float *pPsum, *pRinv;
    cudaGetSymbolAddress((void**)&pQt,   g_Qt);
    cudaGetSymbolAddress((void**)&pKt,   g_Kt);
    cudaGetSymbolAddress((void**)&pVc,   g_Vc);
    cudaGetSymbolAddress((void**)&pP,    g_P);
    cudaGetSymbolAddress((void**)&pPsum, g_psum);
    cudaGetSymbolAddress((void**)&pRinv, g_rinv);

    cudaFuncSetAttribute(gemm1_mma, cudaFuncAttributeMaxDynamicSharedMemorySize, SMEM1_SZ);
    cudaFuncSetAttribute(gemm2_mma, cudaFuncAttributeMaxDynamicSharedMemorySize, SMEM2_SZ);

    // Qt[i][n] = Q[n][i]
    transpose_f2h_v<<<dim3(QDIM / 64, NDIM / 64), 256>>>(q, pQt, NDIM, QDIM);
    // Kt[j][n] = K[n][j]
    transpose_f2h_v<<<dim3(MDIM / 64, NDIM / 64), 256>>>(k, pKt, NDIM, MDIM);
    // Vc straight convert
    {
        size_t n = (size_t)VDIM * MDIM;
        convert_f2h<<<(unsigned)(n / 4 / 256), 256>>>(v, pVc, n);
    }

    // GEMM1 + fused exp + partial row sums
    gemm1_mma<<<dim3(MDIM / BN1, QDIM / BM1), 512, SMEM1_SZ>>>(
        pQt, pKt, pP, pPsum, QDIM, MDIM, NDIM);

    // reduce partials -> reciprocals
    rowsum_recip2<<<QDIM / 8, 256>>>(pPsum, pRinv);

    // GEMM2 + fused normalize
    gemm2_mma<<<dim3(VDIM / BN2, QDIM / BM2), 512, SMEM2_SZ>>>(
        pP, pVc, out, QDIM, VDIM, MDIM, pRinv);
}

// round 15
// speedup vs baseline: 1.0882x; 1.0024x over previous
#include <cuda_runtime.h>
#include <cuda_fp16.h>
#include <cstdint>

#define QDIM 4096   // q_dim (output rows i)
#define NDIM 4096   // contraction of GEMM1 (n)
#define MDIM 8192   // softmax dim / contraction of GEMM2 (j)
#define VDIM 4096   // v_dim (output cols v)
#define GX1  (MDIM / 256)   // GEMM1 grid.x = 32 partials per row

// ---------------- scratch (static device globals) ---------------------------
__device__ __half g_Qt[(size_t)QDIM * NDIM];   // Qt[i][n] = Q[n][i]
__device__ __half g_Kt[(size_t)MDIM * NDIM];   // Kt[j][n] = K[n][j]
__device__ __half g_Vc[(size_t)VDIM * MDIM];   // Vc[v][j] = V[v][j]
__device__ __half g_P [(size_t)QDIM * MDIM];   // exp(s) UNNORMALIZED fp16
__device__ float  g_psum[(size_t)QDIM * GX1];  // per-CTA partial row sums
__device__ float  g_rinv[QDIM];                // 1 / row sums

// ---------------- helpers ----------------------------------------------------
__device__ __forceinline__ uint32_t smem_u32(const void* p) {
    uint32_t a;
    asm("{ .reg .u64 t; cvta.to.shared.u64 t, %1; cvt.u32.u64 %0, t; }" : "=r"(a) : "l"(p));
    return a;
}
__device__ __forceinline__ void cp16(uint32_t dst, const void* src) {
    asm volatile("cp.async.cg.shared.global [%0], [%1], 16;" :: "r"(dst), "l"(src));
}
__device__ __forceinline__ void ldsm4(uint32_t& r0, uint32_t& r1, uint32_t& r2, uint32_t& r3,
                                      uint32_t addr) {
    asm volatile("ldmatrix.sync.aligned.m8n8.x4.shared.b16 {%0,%1,%2,%3}, [%4];"
                 : "=r"(r0), "=r"(r1), "=r"(r2), "=r"(r3) : "r"(addr));
}
__device__ __forceinline__ void mma16816(float* d, uint32_t a0, uint32_t a1, uint32_t a2,
                                         uint32_t a3, uint32_t b0, uint32_t b1) {
    asm volatile(
        "mma.sync.aligned.m16n8k16.row.col.f32.f16.f16.f32 "
        "{%0,%1,%2,%3}, {%4,%5,%6,%7}, {%8,%9}, {%0,%1,%2,%3};"
        : "+f"(d[0]), "+f"(d[1]), "+f"(d[2]), "+f"(d[3])
        : "r"(a0), "r"(a1), "r"(a2), "r"(a3), "r"(b0), "r"(b1));
}

// ---------------- preprocessing ----------------------------------------------
// Vectorized 64x64 transpose: out[c][r] = (half) in[r][c].
__global__ __launch_bounds__(256)
void transpose_f2h_v(const float* __restrict__ in, __half* __restrict__ out,
                     int rows, int cols) {
    __shared__ float tile[64][65];
    const int c0 = blockIdx.x * 64, r0 = blockIdx.y * 64;
    const int tid = threadIdx.x;
    const int lr = tid >> 4, lc = tid & 15;
    #pragma unroll
    for (int i = 0; i < 4; i++) {
        int r = lr + i * 16;
        float4 v = *reinterpret_cast<const float4*>(&in[(size_t)(r0 + r) * cols + c0 + lc * 4]);
        tile[r][lc * 4 + 0] = v.x; tile[r][lc * 4 + 1] = v.y;
        tile[r][lc * 4 + 2] = v.z; tile[r][lc * 4 + 3] = v.w;
    }
    __syncthreads();
    const int oc = tid >> 3, och = tid & 7;
    #pragma unroll
    for (int i = 0; i < 2; i++) {
        int c = oc + i * 32;
        __half h[8];
        #pragma unroll
        for (int j = 0; j < 8; j++) h[j] = __float2half(tile[och * 8 + j][c]);
        *reinterpret_cast<uint4*>(&out[(size_t)(c0 + c) * rows + r0 + och * 8]) =
            *reinterpret_cast<uint4*>(h);
    }
}

__global__ void convert_f2h(const float* __restrict__ in, __half* __restrict__ out, size_t n) {
    size_t i = ((size_t)blockIdx.x * blockDim.x + threadIdx.x) * 4;
    if (i + 3 < n) {
        float4 v = *reinterpret_cast<const float4*>(in + i);
        *reinterpret_cast<__half2*>(out + i)     = __floats2half2_rn(v.x, v.y);
        *reinterpret_cast<__half2*>(out + i + 2) = __floats2half2_rn(v.z, v.w);
    }
}

// =============================================================================
// GEMM1 (R13 measured 702us): 512 thr, 128x256, warp 32x64, 4 stages,
// mainloop unrolled by 4. C = exp(scale*acc) fp16 + fused psum.
// =============================================================================
#define BM1 128
#define BN1 256
#define BKC 64
#define STAGES1 4
#define STG1_BYTES ((BM1 + BN1) * 128)        // 48 KB
#define SMEM1_SZ (STAGES1 * STG1_BYTES)       // 192 KB

__global__ __launch_bounds__(512, 1)
void gemm1_mma(const __half* __restrict__ A, const __half* __restrict__ B,
               __half* __restrict__ C, float* __restrict__ psum,
               int M, int N, int K) {
    extern __shared__ char smem[];
    const uint32_t sb = smem_u32(smem);
    const int tid = threadIdx.x;
    const int wid = tid >> 5;
    const int lane = tid & 31;
    const int wm = wid & 3;            // 4 warps over M -> 32 rows
    const int wn = wid >> 2;           // 4 warps over N -> 64 cols
    const size_t m0 = (size_t)blockIdx.y * BM1;
    const size_t n0 = (size_t)blockIdx.x * BN1;
    const int nk = K / BKC;            // 64 (divisible by 4)

    const int ldrow = tid >> 3;
    const int ldc16 = tid & 7;
    const uint32_t swz_st = ((uint32_t)ldc16 ^ ((uint32_t)ldrow & 7)) << 4;

    auto load_stage = [&](int c, int buf) {
        const uint32_t abase = sb + buf * STG1_BYTES;
        const uint32_t bbase = abase + BM1 * 128;
        const size_t k0 = (size_t)c * BKC;
        #pragma unroll
        for (int i = 0; i < 2; i++) {
            int row = ldrow + i * 64;
            cp16(abase + row * 128 + swz_st, A + (m0 + row) * (size_t)K + k0 + ldc16 * 8);
        }
        #pragma unroll
        for (int i = 0; i < 4; i++) {
            int row = ldrow + i * 64;
            cp16(bbase + row * 128 + swz_st, B + (n0 + row) * (size_t)K + k0 + ldc16 * 8);
        }
        asm volatile("cp.async.commit_group;" ::: "memory");
    };

    float acc[2][8][4];
    #pragma unroll
    for (int i = 0; i < 2; i++)
        #pragma unroll
        for (int j = 0; j < 8; j++)
            #pragma unroll
            for (int r = 0; r < 4; r++) acc[i][j][r] = 0.0f;

    #pragma unroll
    for (int s = 0; s < STAGES1 - 1; s++) load_stage(s, s);

    const uint32_t lrow = lane & 15;
    const uint32_t lhalf = lane >> 4;
    const uint32_t lswz = lane & 7;
    const uint32_t a_rowbyte = (wm * 32 + lrow) * 128;
    const uint32_t b_rowbyte = (wn * 64 + lrow) * 128;
    uint32_t coff[4];
    #pragma unroll
    for (int k16 = 0; k16 < 4; k16++)
        coff[k16] = (((uint32_t)k16 * 2 + lhalf) ^ lswz) << 4;

    for (int it0 = 0; it0 < nk; it0 += STAGES1) {
        #pragma unroll
        for (int u = 0; u < STAGES1; u++) {
            const int it = it0 + u;
            const int rem = nk - 1 - it;
            if (rem >= 2)      asm volatile("cp.async.wait_group 2;" ::: "memory");
            else if (rem == 1) asm volatile("cp.async.wait_group 1;" ::: "memory");
            else               asm volatile("cp.async.wait_group 0;" ::: "memory");
            __syncthreads();
            if (it + STAGES1 - 1 < nk)
                load_stage(it + STAGES1 - 1, (u + STAGES1 - 1) % STAGES1);

            const uint32_t abase = sb + u * STG1_BYTES;      // compile-time
            const uint32_t bbase = abase + BM1 * 128;

            #pragma unroll
            for (int k16 = 0; k16 < 4; k16++) {
                uint32_t a[2][4], b[4][4];
                #pragma unroll
                for (int mi = 0; mi < 2; mi++)
                    ldsm4(a[mi][0], a[mi][1], a[mi][2], a[mi][3],
                          abase + a_rowbyte + mi * 2048 + coff[k16]);
                #pragma unroll
                for (int ni = 0; ni < 4; ni++)
                    ldsm4(b[ni][0], b[ni][1], b[ni][2], b[ni][3],
                          bbase + b_rowbyte + ni * 2048 + coff[k16]);
                #pragma unroll
                for (int mi = 0; mi < 2; mi++)
                    #pragma unroll
                    for (int nj = 0; nj < 8; nj++)
                        mma16816(acc[mi][nj], a[mi][0], a[mi][1], a[mi][2], a[mi][3],
                                 b[nj >> 1][nj & 1], b[nj >> 1][(nj & 1) + 2]);
            }
        }
    }

    // ---- epilogue: store exp, accumulate per-row partial sums ---------------
    const float scale = 0.015625f;     // 1/sqrt(4096)
    float s0[2], s1[2];
    #pragma unroll
    for (int mi = 0; mi < 2; mi++) { s0[mi] = 0.0f; s1[mi] = 0.0f; }
    #pragma unroll
    for (int mi = 0; mi < 2; mi++) {
        const size_t r0 = m0 + wm * 32 + mi * 16 + (lane >> 2);
        const size_t r1 = r0 + 8;
        #pragma unroll
        for (int nj = 0; nj < 8; nj++) {
            const size_t col = n0 + wn * 64 + nj * 8 + (lane & 3) * 2;
            float* c = acc[mi][nj];
            float e0 = __expf(c[0] * scale), e1 = __expf(c[1] * scale);
            float e2 = __expf(c[2] * scale), e3 = __expf(c[3] * scale);
            *reinterpret_cast<__half2*>(&C[r0 * (size_t)N + col]) = __floats2half2_rn(e0, e1);
            *reinterpret_cast<__half2*>(&C[r1 * (size_t)N + col]) = __floats2half2_rn(e2, e3);
            s0[mi] += e0 + e1;
            s1[mi] += e2 + e3;
        }
    }
    float* red = reinterpret_cast<float*>(smem);
    __syncthreads();
    #pragma unroll
    for (int mi = 0; mi < 2; mi++) {
        float a = s0[mi], b = s1[mi];
        a += __shfl_xor_sync(0xFFFFFFFFu, a, 1);
        a += __shfl_xor_sync(0xFFFFFFFFu, a, 2);
        b += __shfl_xor_sync(0xFFFFFFFFu, b, 1);
        b += __shfl_xor_sync(0xFFFFFFFFu, b, 2);
        if ((lane & 3) == 0) {
            int rl = wm * 32 + mi * 16 + (lane >> 2);
            red[rl * 4 + wn] = a;
            red[(rl + 8) * 4 + wn] = b;
        }
    }
    __syncthreads();
    if (tid < BM1) {
        float s = red[tid * 4] + red[tid * 4 + 1] + red[tid * 4 + 2] + red[tid * 4 + 3];
        psum[(m0 + tid) * GX1 + blockIdx.x] = s;
    }
}

// ---------------- reduce psum partials -> rinv -------------------------------
__global__ __launch_bounds__(256)
void rowsum_recip2(const float* __restrict__ psum, float* __restrict__ rinv) {
    const int row = blockIdx.x * 8 + (threadIdx.x >> 5);
    const int lane = threadIdx.x & 31;
    float v = psum[(size_t)row * GX1 + lane];
    #pragma unroll
    for (int o = 16; o > 0; o >>= 1) v += __shfl_xor_sync(0xFFFFFFFFu, v, o);
    if (lane == 0) rinv[row] = 1.0f / v;
}

// =============================================================================
// GEMM2: 512 thr, 128x128, warp 32x32, 3 stages, 2 CTAs/SM.
// Mainloop unrolled by 3 with per-sub-iter guard (nk=128 = 42*3 + 2).
// C = acc * rinv[row] fp32
// =============================================================================
#define BM2 128
#define BN2 128
#define STAGES2 3
#define STG2_BYTES ((BM2 + BN2) * 128)        // 32 KB
#define SMEM2_SZ (STAGES2 * STG2_BYTES)       // 96 KB

__global__ __launch_bounds__(512, 2)
void gemm2_mma(const __half* __restrict__ A, const __half* __restrict__ B,
               float* __restrict__ C, int M, int N, int K,
               const float* __restrict__ rinv) {
    extern __shared__ char smem[];
    const uint32_t sb = smem_u32(smem);
    const int tid = threadIdx.x;
    const int wid = tid >> 5;          // 0..15
    const int lane = tid & 31;
    const int wm = wid & 3;            // 4 warps over M -> 32 rows
    const int wn = wid >> 2;           // 4 warps over N -> 32 cols
    const size_t m0 = (size_t)blockIdx.y * BM2;
    const size_t n0 = (size_t)blockIdx.x * BN2;
    const int nk = K / BKC;            // 128

    const int ldrow = tid >> 3;        // 0..63
    const int ldc16 = tid & 7;
    const uint32_t swz_st = ((uint32_t)ldc16 ^ ((uint32_t)ldrow & 7)) << 4;

    auto load_stage = [&](int c, int buf) {
        const uint32_t abase = sb + buf * STG2_BYTES;
        const uint32_t bbase = abase + BM2 * 128;
        const size_t k0 = (size_t)c * BKC;
        #pragma unroll
        for (int i = 0; i < 2; i++) {
            int row = ldrow + i * 64;
            cp16(abase + row * 128 + swz_st, A + (m0 + row) * (size_t)K + k0 + ldc16 * 8);
        }
        #pragma unroll
        for (int i = 0; i < 2; i++) {
            int row = ldrow + i * 64;
            cp16(bbase + row * 128 + swz_st, B + (n0 + row) * (size_t)K + k0 + ldc16 * 8);
        }
        asm volatile("cp.async.commit_group;" ::: "memory");
    };

    float acc[2][4][4];
    #pragma unroll
    for (int i = 0; i < 2; i++)
        #pragma unroll
        for (int j = 0; j < 4; j++)
            #pragma unroll
            for (int r = 0; r < 4; r++) acc[i][j][r] = 0.0f;

    #pragma unroll
    for (int s = 0; s < STAGES2 - 1; s++) load_stage(s, s);

    const uint32_t lrow = lane & 15;
    const uint32_t lhalf = lane >> 4;
    const uint32_t lswz = lane & 7;
    const uint32_t a_rowbyte = (wm * 32 + lrow) * 128;
    const uint32_t b_rowbyte = (wn * 32 + lrow) * 128;
    uint32_t coff[4];
    #pragma unroll
    for (int k16 = 0; k16 < 4; k16++)
        coff[k16] = (((uint32_t)k16 * 2 + lhalf) ^ lswz) << 4;

    // unrolled by STAGES2 with guard: buffer index u is compile-time
    for (int it0 = 0; it0 < nk; it0 += STAGES2) {
        #pragma unroll
        for (int u = 0; u < STAGES2; u++) {
            const int it = it0 + u;
            if (it < nk) {
                if (it + 1 < nk) asm volatile("cp.async.wait_group 1;" ::: "memory");
                else             asm volatile("cp.async.wait_group 0;" ::: "memory");
                __syncthreads();
                if (it + STAGES2 - 1 < nk)
                    load_stage(it + STAGES2 - 1, (u + STAGES2 - 1) % STAGES2);

                const uint32_t abase = sb + u * STG2_BYTES;   // compile-time
                const uint32_t bbase = abase + BM2 * 128;

                #pragma unroll
                for (int k16 = 0; k16 < 4; k16++) {
                    uint32_t a[2][4], b[2][4];
                    #pragma unroll
                    for (int mi = 0; mi < 2; mi++)
                        ldsm4(a[mi][0], a[mi][1], a[mi][2], a[mi][3],
                              abase + a_rowbyte + mi * 2048 + coff[k16]);
                    #pragma unroll
                    for (int ni = 0; ni < 2; ni++)
                        ldsm4(b[ni][0], b[ni][1], b[ni][2], b[ni][3],
                              bbase + b_rowbyte + ni * 2048 + coff[k16]);
                    #pragma unroll
                    for (int mi = 0; mi < 2; mi++)
                        #pragma unroll
                        for (int nj = 0; nj < 4; nj++)
                            mma16816(acc[mi][nj], a[mi][0], a[mi][1], a[mi][2], a[mi][3],
                                     b[nj >> 1][nj & 1], b[nj >> 1][(nj & 1) + 2]);
                }
            }
        }
    }

    #pragma unroll
    for (int mi = 0; mi < 2; mi++) {
        const size_t r0 = m0 + wm * 32 + mi * 16 + (lane >> 2);
        const size_t r1 = r0 + 8;
        const float i0 = rinv[r0];
        const float i1 = rinv[r1];
        #pragma unroll
        for (int nj = 0; nj < 4; nj++) {
            const size_t col = n0 + wn * 32 + nj * 8 + (lane & 3) * 2;
            float* c = acc[mi][nj];
            *reinterpret_cast<float2*>(&C[r0 * (size_t)N + col]) =
                make_float2(c[0] * i0, c[1] * i0);
            *reinterpret_cast<float2*>(&C[r1 * (size_t)N + col]) =
                make_float2(c[2] * i1, c[3] * i1);
        }
    }
}

// ---------------- launch ------------------------------------------------------
extern "C" void kernel_launch(void* const* d_in, const int* in_sizes, int n_in,
                              void* d_out, int out_size) {
    const float* q = (const float*)d_in[0];   // (4096, 4096)  Q[n][i]
    const float* k = (const float*)d_in[1];   // (4096, 8192)  K[n][j]
    const float* v = (const float*)d_in[2];   // (4096, 8192)  V[v][j]
    float* out = (float*)d_out;               // (4096, 4096)  out[i][v]

    __half *pQt, *pKt, *pVc, *pP;
    float *pPsum, *pRinv;
    cudaGetSymbolAddress((void**)&pQt,   g_Qt);
    cudaGetSymbolAddress((void**)&pKt,   g_Kt);
    cudaGetSymbolAddress((void**)&pVc,   g_Vc);
    cudaGetSymbolAddress((void**)&pP,    g_P);
    cudaGetSymbolAddress((void**)&pPsum, g_psum);
    cudaGetSymbolAddress((void**)&pRinv, g_rinv);

    cudaFuncSetAttribute(gemm1_mma, cudaFuncAttributeMaxDynamicSharedMemorySize, SMEM1_SZ);
    cudaFuncSetAttribute(gemm2_mma, cudaFuncAttributeMaxDynamicSharedMemorySize, SMEM2_SZ);

    // Qt[i][n] = Q[n][i]
    transpose_f2h_v<<<dim3(QDIM / 64, NDIM / 64), 256>>>(q, pQt, NDIM, QDIM);
    // Kt[j][n] = K[n][j]
    transpose_f2h_v<<<dim3(MDIM / 64, NDIM / 64), 256>>>(k, pKt, NDIM, MDIM);
    // Vc straight convert
    {
        size_t n = (size_t)VDIM * MDIM;
        convert_f2h<<<(unsigned)(n / 4 / 256), 256>>>(v, pVc, n);
    }

    // GEMM1 + fused exp + partial row sums
    gemm1_mma<<<dim3(MDIM / BN1, QDIM / BM1), 512, SMEM1_SZ>>>(
        pQt, pKt, pP, pPsum, QDIM, MDIM, NDIM);

    // reduce partials -> reciprocals
    rowsum_recip2<<<QDIM / 8, 256>>>(pPsum, pRinv);

    // GEMM2 + fused normalize
    gemm2_mma<<<dim3(VDIM / BN2, QDIM / BM2), 512, SMEM2_SZ>>>(
        pP, pVc, out, QDIM, VDIM, MDIM, pRinv);
}